// round 1
// baseline (speedup 1.0000x reference)
#include <cuda_runtime.h>
#include <math.h>

#define N 8192
#define D 256
#define NLAB 8
#define BM 128
#define BN 128
#define BK 16

// ---- device global scratch (no allocations allowed) ----
__device__ float g_Fs[N * D];     // sorted, normalized features (8 MB)
__device__ int   g_pos[N];        // original row -> sorted position
__device__ int   g_lab_s[N];      // sorted labels
__device__ int   g_spk_s[N];      // sorted speaker ids
__device__ float g_num[N];
__device__ float g_den[N];
__device__ float g_total;
__device__ int   g_count;

// ------------------------------------------------------------------
__global__ void zero_kernel() {
    int i = blockIdx.x * blockDim.x + threadIdx.x;
    if (i < N) { g_num[i] = 0.f; g_den[i] = 0.f; }
    if (i == 0) { g_total = 0.f; g_count = 0; }
}

// ------------------------------------------------------------------
// Single-block deterministic counting sort by label (8 buckets).
// Also auto-detects whether labels/speaker_ids arrived as int32 or int64:
// if int64 (little-endian, values < 2^31), every odd 32-bit word within the
// first 8192 words is a zero high-half. For int32 data those words are real
// labels -- probability all 4096 are zero is (1/8)^4096 ~ 0.
__global__ void sort_kernel(const int* __restrict__ lab32,
                            const int* __restrict__ spk32) {
    __shared__ int sh_cnt[256][NLAB];
    __shared__ int sh_tot[NLAB];
    __shared__ int sh_bucket[NLAB];
    __shared__ int sh_flag;
    const int t = threadIdx.x;

    if (t == 0) sh_flag = 0;
    __syncthreads();

    int anynz = 0;
    #pragma unroll
    for (int j = 0; j < 16; j++) {
        int idx = 2 * (t * 16 + j) + 1;   // odd words 1..8191
        anynz |= lab32[idx];
    }
    if (anynz) atomicOr(&sh_flag, 1);
    __syncthreads();
    const int is64 = (sh_flag == 0);

    const int base = t * 32;
    int cnt[NLAB];
    #pragma unroll
    for (int l = 0; l < NLAB; l++) cnt[l] = 0;
    for (int j = 0; j < 32; j++) {
        int i = base + j;
        int l = is64 ? lab32[2 * i] : lab32[i];
        cnt[l]++;
    }
    #pragma unroll
    for (int l = 0; l < NLAB; l++) sh_cnt[t][l] = cnt[l];
    __syncthreads();

    // exclusive scan over the 256 chunks, one label per thread
    if (t < NLAB) {
        int run = 0;
        for (int c = 0; c < 256; c++) {
            int v = sh_cnt[c][t];
            sh_cnt[c][t] = run;
            run += v;
        }
        sh_tot[t] = run;
    }
    __syncthreads();
    if (t == 0) {
        int run = 0;
        for (int l = 0; l < NLAB; l++) { sh_bucket[l] = run; run += sh_tot[l]; }
    }
    __syncthreads();

    int run[NLAB];
    #pragma unroll
    for (int l = 0; l < NLAB; l++) run[l] = sh_bucket[l] + sh_cnt[t][l];
    for (int j = 0; j < 32; j++) {
        int i = base + j;
        int l = is64 ? lab32[2 * i] : lab32[i];
        int s = is64 ? spk32[2 * i] : spk32[i];
        int p = run[l]++;
        g_pos[i]   = p;
        g_lab_s[p] = l;
        g_spk_s[p] = s;
    }
}

// ------------------------------------------------------------------
// One block (64 threads) per row: L2-normalize and scatter to sorted pos.
__global__ void gather_norm_kernel(const float* __restrict__ feat) {
    const int row = blockIdx.x;
    const int t = threadIdx.x;  // 64 threads, D/4 = 64 float4s
    float4 v = reinterpret_cast<const float4*>(feat + (size_t)row * D)[t];
    float ss = v.x * v.x + v.y * v.y + v.z * v.z + v.w * v.w;
    #pragma unroll
    for (int o = 16; o; o >>= 1) ss += __shfl_xor_sync(0xffffffffu, ss, o);
    __shared__ float sw[2];
    if ((t & 31) == 0) sw[t >> 5] = ss;
    __syncthreads();
    float inv = 1.f / fmaxf(sqrtf(sw[0] + sw[1]), 1e-12f);
    int p = g_pos[row];
    float4 o4 = make_float4(v.x * inv, v.y * inv, v.z * inv, v.w * inv);
    reinterpret_cast<float4*>(g_Fs + (size_t)p * D)[t] = o4;
}

// ------------------------------------------------------------------
// Banded tiled SGEMM (sim = F F^T, sorted domain) fused with the NTXent
// epilogue. Tiles whose row/col label ranges don't intersect are skipped.
__global__ void __launch_bounds__(256) gemm_epilogue_kernel() {
    const int rs = blockIdx.y * BM;
    const int cs = blockIdx.x * BN;

    // band skip: labels sorted ascending
    if (g_lab_s[cs] > g_lab_s[rs + BM - 1] ||
        g_lab_s[cs + BN - 1] < g_lab_s[rs]) return;

    __shared__ float As[BK][BM];
    __shared__ float Bs[BK][BN];
    __shared__ int labn[BN];
    __shared__ int spkn[BN];

    const int t  = threadIdx.x;
    const int tx = t & 15;
    const int ty = t >> 4;

    if (t < BN) { labn[t] = g_lab_s[cs + t]; spkn[t] = g_spk_s[cs + t]; }

    float acc[8][8];
    #pragma unroll
    for (int i = 0; i < 8; i++)
        #pragma unroll
        for (int j = 0; j < 8; j++) acc[i][j] = 0.f;

    for (int kt = 0; kt < D; kt += BK) {
        #pragma unroll
        for (int q0 = 0; q0 < 2; q0++) {
            int q   = t + q0 * 256;        // 0..511
            int row = q >> 2;              // 0..127
            int kq  = (q & 3) * 4;         // 0,4,8,12
            float4 a = *reinterpret_cast<const float4*>(
                g_Fs + (size_t)(rs + row) * D + kt + kq);
            As[kq][row] = a.x; As[kq + 1][row] = a.y;
            As[kq + 2][row] = a.z; As[kq + 3][row] = a.w;
            float4 b = *reinterpret_cast<const float4*>(
                g_Fs + (size_t)(cs + row) * D + kt + kq);
            Bs[kq][row] = b.x; Bs[kq + 1][row] = b.y;
            Bs[kq + 2][row] = b.z; Bs[kq + 3][row] = b.w;
        }
        __syncthreads();
        #pragma unroll
        for (int k = 0; k < BK; k++) {
            float a[8], b[8];
            *reinterpret_cast<float4*>(a)     = *reinterpret_cast<float4*>(&As[k][ty * 8]);
            *reinterpret_cast<float4*>(a + 4) = *reinterpret_cast<float4*>(&As[k][ty * 8 + 4]);
            *reinterpret_cast<float4*>(b)     = *reinterpret_cast<float4*>(&Bs[k][tx * 8]);
            *reinterpret_cast<float4*>(b + 4) = *reinterpret_cast<float4*>(&Bs[k][tx * 8 + 4]);
            #pragma unroll
            for (int i = 0; i < 8; i++)
                #pragma unroll
                for (int j = 0; j < 8; j++)
                    acc[i][j] = fmaf(a[i], b[j], acc[i][j]);
        }
        __syncthreads();
    }

    // epilogue: exp + masked accumulation
    const float invT = 1.25f;  // 1 / 0.8
    #pragma unroll
    for (int i = 0; i < 8; i++) {
        int gi = rs + ty * 8 + i;
        int li = g_lab_s[gi];
        int si = g_spk_s[gi];
        float num = 0.f, den = 0.f;
        #pragma unroll
        for (int j = 0; j < 8; j++) {
            int cj = tx * 8 + j;
            int gj = cs + cj;
            if (labn[cj] == li && gi != gj) {
                float e = __expf(acc[i][j] * invT);
                den += e;
                if (spkn[cj] == si) num += e;
            }
        }
        if (den != 0.f) atomicAdd(&g_den[gi], den);
        if (num != 0.f) atomicAdd(&g_num[gi], num);
    }
}

// ------------------------------------------------------------------
__global__ void finalize_kernel() {
    int i = blockIdx.x * blockDim.x + threadIdx.x;
    float loss = 0.f;
    int c = 0;
    if (i < N) {
        float num = g_num[i];
        float den = g_den[i] + 1e-7f;
        if (num > 0.f) { loss = -(logf(num) - logf(den)); c = 1; }
    }
    #pragma unroll
    for (int o = 16; o; o >>= 1) {
        loss += __shfl_xor_sync(0xffffffffu, loss, o);
        c    += __shfl_xor_sync(0xffffffffu, c, o);
    }
    __shared__ float sl[8];
    __shared__ int   sc[8];
    int lane = threadIdx.x & 31, w = threadIdx.x >> 5;
    if (lane == 0) { sl[w] = loss; sc[w] = c; }
    __syncthreads();
    if (threadIdx.x == 0) {
        float tl = 0.f; int tc = 0;
        for (int q = 0; q < 8; q++) { tl += sl[q]; tc += sc[q]; }
        atomicAdd(&g_total, tl);
        atomicAdd(&g_count, tc);
    }
}

__global__ void write_out_kernel(float* out) {
    out[0] = (g_count > 0) ? g_total / (float)g_count : 0.f;
}

// ------------------------------------------------------------------
extern "C" void kernel_launch(void* const* d_in, const int* in_sizes, int n_in,
                              void* d_out, int out_size) {
    const float* feat = (const float*)d_in[0];
    const int*   lab  = (const int*)d_in[1];
    const int*   spk  = (const int*)d_in[2];
    float* out = (float*)d_out;

    zero_kernel<<<32, 256>>>();
    sort_kernel<<<1, 256>>>(lab, spk);
    gather_norm_kernel<<<N, 64>>>(feat);
    dim3 grid(N / BN, N / BM);
    gemm_epilogue_kernel<<<grid, 256>>>();
    finalize_kernel<<<32, 256>>>();
    write_out_kernel<<<1, 1>>>(out);
}